// round 1
// baseline (speedup 1.0000x reference)
#include <cuda_runtime.h>
#include <cuda_bf16.h>

// ---------------- problem constants ----------------
#define NODES 50000
#define RELS  3
#define EDGES 600000
#define D_IN  128
#define D_HID 256
#define D_OUT 128

// ---------------- scratch (static device globals; no allocs allowed) ----------------
__device__ float g_seg1[(size_t)RELS * NODES * D_IN];    // 76.8 MB
__device__ float g_seg2[(size_t)RELS * NODES * D_HID];   // 153.6 MB
__device__ float g_h   [(size_t)NODES * D_HID];          // 51.2 MB
__device__ float g_A1  [(size_t)NODES * 4 * D_IN];       // 102.4 MB
__device__ float g_A2  [(size_t)NODES * 4 * D_HID];      // 204.8 MB
__device__ float g_rinv[(size_t)RELS * NODES];           // deg then 1/max(deg,1)
__device__ float g_W1  [4 * D_IN * D_HID];               // 512 x 256
__device__ float g_W2  [4 * D_HID * D_OUT];              // 1024 x 128
__device__ float g_b1s [D_HID];
__device__ float g_b2s [D_OUT];

// ---------------- utility kernels ----------------
__global__ void zero_kernel(float4* __restrict__ p, long n4) {
    long stride = (long)gridDim.x * blockDim.x;
    for (long i = (long)blockIdx.x * blockDim.x + threadIdx.x; i < n4; i += stride)
        p[i] = make_float4(0.f, 0.f, 0.f, 0.f);
}

// Build stacked weight Wcat [4*DI, DO]: rows [0,DI) = sum_r Wself_r, rows DI+r*DI+d = Wneigh[r][d].
// Also bias sum bs[j] = sum_r b[r][j].
__global__ void prep_w_kernel(const float* __restrict__ Wself, const float* __restrict__ Wneigh,
                              const float* __restrict__ b, float* __restrict__ Wcat,
                              float* __restrict__ bs, int DI, int DO) {
    int total = 4 * DI * DO;
    int stride = gridDim.x * blockDim.x;
    for (int idx = blockIdx.x * blockDim.x + threadIdx.x; idx < total; idx += stride) {
        int k = idx / DO;
        int j = idx - k * DO;
        float v;
        if (k < DI) {
            v = Wself[k * DO + j] + Wself[(DI + k) * DO + j] + Wself[(2 * DI + k) * DO + j];
        } else {
            int r = (k - DI) / DI;
            int d = (k - DI) - r * DI;
            v = Wneigh[((size_t)r * DI + d) * DO + j];
        }
        Wcat[idx] = v;
    }
    int idx = blockIdx.x * blockDim.x + threadIdx.x;
    if (idx < DO) bs[idx] = b[idx] + b[DO + idx] + b[2 * DO + idx];
}

__global__ void deg_kernel(const int* __restrict__ dst, float* __restrict__ deg) {
    int e = blockIdx.x * blockDim.x + threadIdx.x;
    if (e >= RELS * EDGES) return;
    int r = e / EDGES;
    atomicAdd(&deg[r * NODES + dst[e]], 1.0f);
}

__global__ void rinv_kernel(float* __restrict__ deg) {
    int i = blockIdx.x * blockDim.x + threadIdx.x;
    if (i < RELS * NODES) deg[i] = 1.0f / fmaxf(deg[i], 1.0f);
}

// ---------------- scatter: seg[r][dst] += feat[src], one warp per edge ----------------
template <int D>
__global__ void scatter_kernel(const float* __restrict__ feat, const int* __restrict__ src,
                               const int* __restrict__ dst, float* __restrict__ seg) {
    long gwarp = ((long)blockIdx.x * blockDim.x + threadIdx.x) >> 5;
    int lane = threadIdx.x & 31;
    const long total = (long)RELS * EDGES;
    if (gwarp >= total) return;
    int r = (int)(gwarp / EDGES);
    int s = src[gwarp];
    int d = dst[gwarp];
    const float4* xin = (const float4*)(feat + (size_t)s * D);
    float* out = seg + ((size_t)r * NODES + d) * D;
#pragma unroll
    for (int i = lane; i < D / 4; i += 32) {
        float4 v = __ldg(&xin[i]);
        asm volatile("red.global.add.v4.f32 [%0], {%1,%2,%3,%4};"
                     :: "l"(out + i * 4), "f"(v.x), "f"(v.y), "f"(v.z), "f"(v.w)
                     : "memory");
    }
}

// ---------------- build A = [feat | mean_0 | mean_1 | mean_2], row-major [N, 4D] ----------------
template <int D>
__global__ void buildA_kernel(const float* __restrict__ feat, const float* __restrict__ seg,
                              const float* __restrict__ rinv, float* __restrict__ A) {
    const long total = (long)NODES * D;  // float4 count per full A (4D floats / 4 per row * N)
    long stride = (long)gridDim.x * blockDim.x;
    for (long id = (long)blockIdx.x * blockDim.x + threadIdx.x; id < total; id += stride) {
        int n = (int)(id / D);
        int c4 = (int)(id - (long)n * D);
        int k = c4 * 4;          // float column in [0, 4D)
        int chunk = k / D;       // 0..3
        float4 v;
        if (chunk == 0) {
            v = ((const float4*)(feat + (size_t)n * D))[c4];
        } else {
            int r = chunk - 1;
            int off = k - chunk * D;
            v = *(const float4*)(seg + ((size_t)r * NODES + n) * D + off);
            float sc = rinv[r * NODES + n];
            v.x *= sc; v.y *= sc; v.z *= sc; v.w *= sc;
        }
        ((float4*)A)[id] = v;
    }
}

// ---------------- SGEMM: C[M,N] = act(A[M,K] @ B[K,N] + bias), 128x128x16 tiles ----------------
__global__ __launch_bounds__(256)
void sgemm_kernel(const float* __restrict__ A, const float* __restrict__ B,
                  const float* __restrict__ bias, float* __restrict__ C,
                  int M, int N, int K, int doRelu) {
    const int BM = 128, BN = 128, BK = 16, TM = 8, TN = 8;
    __shared__ float As[BK][BM];
    __shared__ float Bs[BK][BN];
    int tid = threadIdx.x;
    int block_row = blockIdx.x * BM;
    int block_col = blockIdx.y * BN;
    int tcol = (tid % 16) * TN;
    int trow = (tid / 16) * TM;

    float acc[TM][TN];
#pragma unroll
    for (int i = 0; i < TM; i++)
#pragma unroll
        for (int j = 0; j < TN; j++) acc[i][j] = 0.f;

    for (int kb = 0; kb < K; kb += BK) {
#pragma unroll
        for (int l = 0; l < 2; l++) {
            int f = tid * 2 + l;          // 0..511
            // A tile: 128 rows x 16 cols = 512 float4
            int ar = f >> 2;              // 0..127
            int ak = (f & 3) * 4;         // 0,4,8,12
            int gr = block_row + ar;
            float4 av = (gr < M) ? *(const float4*)(A + (size_t)gr * K + kb + ak)
                                 : make_float4(0.f, 0.f, 0.f, 0.f);
            As[ak + 0][ar] = av.x;
            As[ak + 1][ar] = av.y;
            As[ak + 2][ar] = av.z;
            As[ak + 3][ar] = av.w;
            // B tile: 16 rows x 128 cols = 512 float4
            int br = f >> 5;              // 0..15
            int bc = (f & 31) * 4;        // 0..124
            *(float4*)(&Bs[br][bc]) = *(const float4*)(B + (size_t)(kb + br) * N + block_col + bc);
        }
        __syncthreads();
#pragma unroll
        for (int k = 0; k < BK; k++) {
            float a[TM], b[TN];
#pragma unroll
            for (int i = 0; i < TM; i++) a[i] = As[k][trow + i];
#pragma unroll
            for (int j = 0; j < TN; j++) b[j] = Bs[k][tcol + j];
#pragma unroll
            for (int i = 0; i < TM; i++)
#pragma unroll
                for (int j = 0; j < TN; j++) acc[i][j] += a[i] * b[j];
        }
        __syncthreads();
    }

#pragma unroll
    for (int i = 0; i < TM; i++) {
        int gr = block_row + trow + i;
        if (gr >= M) continue;
#pragma unroll
        for (int j = 0; j < TN; j += 4) {
            float4 v;
            v.x = acc[i][j + 0] + bias[block_col + tcol + j + 0];
            v.y = acc[i][j + 1] + bias[block_col + tcol + j + 1];
            v.z = acc[i][j + 2] + bias[block_col + tcol + j + 2];
            v.w = acc[i][j + 3] + bias[block_col + tcol + j + 3];
            if (doRelu) {
                v.x = fmaxf(v.x, 0.f); v.y = fmaxf(v.y, 0.f);
                v.z = fmaxf(v.z, 0.f); v.w = fmaxf(v.w, 0.f);
            }
            *(float4*)(C + (size_t)gr * N + block_col + tcol + j) = v;
        }
    }
}

// ---------------- launch ----------------
extern "C" void kernel_launch(void* const* d_in, const int* in_sizes, int n_in,
                              void* d_out, int out_size) {
    const float* x      = (const float*)d_in[0];   // [N, 128]
    const int*   src    = (const int*)  d_in[1];   // [R, E]
    const int*   dst    = (const int*)  d_in[2];   // [R, E]
    const float* Wself1 = (const float*)d_in[3];   // [R, 128, 256]
    const float* Wneigh1= (const float*)d_in[4];   // [R, 128, 256]
    const float* b1     = (const float*)d_in[5];   // [R, 256]
    const float* Wself2 = (const float*)d_in[6];   // [R, 256, 128]
    const float* Wneigh2= (const float*)d_in[7];   // [R, 256, 128]
    const float* b2     = (const float*)d_in[8];   // [R, 128]
    float* out = (float*)d_out;                    // [N, 128]

    float *seg1, *seg2, *h, *A1, *A2, *rinv, *W1, *W2, *b1s, *b2s;
    cudaGetSymbolAddress((void**)&seg1, g_seg1);
    cudaGetSymbolAddress((void**)&seg2, g_seg2);
    cudaGetSymbolAddress((void**)&h,    g_h);
    cudaGetSymbolAddress((void**)&A1,   g_A1);
    cudaGetSymbolAddress((void**)&A2,   g_A2);
    cudaGetSymbolAddress((void**)&rinv, g_rinv);
    cudaGetSymbolAddress((void**)&W1,   g_W1);
    cudaGetSymbolAddress((void**)&W2,   g_W2);
    cudaGetSymbolAddress((void**)&b1s,  g_b1s);
    cudaGetSymbolAddress((void**)&b2s,  g_b2s);

    // ---- zero accumulators + deg ----
    {
        long n4;
        n4 = (long)RELS * NODES * D_IN / 4;
        zero_kernel<<<4096, 256>>>((float4*)seg1, n4);
        n4 = (long)RELS * NODES * D_HID / 4;
        zero_kernel<<<4096, 256>>>((float4*)seg2, n4);
        // rinv holds RELS*NODES = 150000 floats (not /4-friendly? 150000/4=37500, ok)
        zero_kernel<<<256, 256>>>((float4*)rinv, (long)RELS * NODES / 4);
    }

    // ---- stacked weights / bias ----
    prep_w_kernel<<<(4 * D_IN * D_HID + 255) / 256, 256>>>(Wself1, Wneigh1, b1, W1, b1s, D_IN, D_HID);
    prep_w_kernel<<<(4 * D_HID * D_OUT + 255) / 256, 256>>>(Wself2, Wneigh2, b2, W2, b2s, D_HID, D_OUT);

    // ---- degrees -> reciprocal ----
    deg_kernel<<<(RELS * EDGES + 255) / 256, 256>>>(dst, rinv);
    rinv_kernel<<<(RELS * NODES + 255) / 256, 256>>>(rinv);

    const long total_edges = (long)RELS * EDGES;
    const int scatter_blocks = (int)((total_edges * 32 + 255) / 256);

    // ---- layer 1 ----
    scatter_kernel<D_IN><<<scatter_blocks, 256>>>(x, src, dst, seg1);
    buildA_kernel<D_IN><<<16384, 256>>>(x, seg1, rinv, A1);
    {
        dim3 grid((NODES + 127) / 128, D_HID / 128);
        sgemm_kernel<<<grid, 256>>>(A1, W1, b1s, h, NODES, D_HID, 4 * D_IN, 1);
    }

    // ---- layer 2 ----
    scatter_kernel<D_HID><<<scatter_blocks, 256>>>(h, src, dst, seg2);
    buildA_kernel<D_HID><<<16384, 256>>>(h, seg2, rinv, A2);
    {
        dim3 grid((NODES + 127) / 128, D_OUT / 128);
        sgemm_kernel<<<grid, 256>>>(A2, W2, b2s, out, NODES, D_OUT, 4 * D_HID, 0);
    }
}

// round 2
// speedup vs baseline: 1.5968x; 1.5968x over previous
#include <cuda_runtime.h>
#include <cuda_bf16.h>
#include <cstdint>

// ---------------- problem constants ----------------
#define NODES 50000
#define RELS  3
#define EDGES 600000
#define D_IN  128
#define D_HID 256
#define D_OUT 128

// ---------------- scratch ----------------
__device__ float g_seg1[(size_t)RELS * NODES * D_IN];    // 76.8 MB
__device__ float g_seg2[(size_t)RELS * NODES * D_HID];   // 153.6 MB
__device__ float g_h   [(size_t)NODES * D_HID];          // 51.2 MB
__device__ float g_rinv[(size_t)RELS * NODES];
__device__ float g_W1  [4 * D_IN * D_HID];               // 512 x 256 (tf32 bits)
__device__ float g_W2  [4 * D_HID * D_OUT];              // 1024 x 128 (tf32 bits)
__device__ float g_b1s [D_HID];
__device__ float g_b2s [D_OUT];

__device__ __forceinline__ unsigned f2tf32(float x) {
    unsigned r;
    asm("cvt.rna.tf32.f32 %0, %1;" : "=r"(r) : "f"(x));
    return r;
}

// ---------------- utility kernels ----------------
__global__ void zero_kernel(float4* __restrict__ p, long n4) {
    long stride = (long)gridDim.x * blockDim.x;
    for (long i = (long)blockIdx.x * blockDim.x + threadIdx.x; i < n4; i += stride)
        p[i] = make_float4(0.f, 0.f, 0.f, 0.f);
}

// Wcat [4*DI, DO] in tf32 (rounded, stored as fp32 bit pattern). bias sum in fp32.
__global__ void prep_w_kernel(const float* __restrict__ Wself, const float* __restrict__ Wneigh,
                              const float* __restrict__ b, float* __restrict__ Wcat,
                              float* __restrict__ bs, int DI, int DO) {
    int total = 4 * DI * DO;
    int stride = gridDim.x * blockDim.x;
    for (int idx = blockIdx.x * blockDim.x + threadIdx.x; idx < total; idx += stride) {
        int k = idx / DO;
        int j = idx - k * DO;
        float v;
        if (k < DI) {
            v = Wself[k * DO + j] + Wself[(DI + k) * DO + j] + Wself[(2 * DI + k) * DO + j];
        } else {
            int r = (k - DI) / DI;
            int d = (k - DI) - r * DI;
            v = Wneigh[((size_t)r * DI + d) * DO + j];
        }
        unsigned t = f2tf32(v);
        Wcat[idx] = __uint_as_float(t);
    }
    int idx = blockIdx.x * blockDim.x + threadIdx.x;
    if (idx < DO) bs[idx] = b[idx] + b[DO + idx] + b[2 * DO + idx];
}

__global__ void deg_kernel(const int* __restrict__ dst, float* __restrict__ deg) {
    int e = blockIdx.x * blockDim.x + threadIdx.x;
    if (e >= RELS * EDGES) return;
    int r = e / EDGES;
    atomicAdd(&deg[r * NODES + dst[e]], 1.0f);
}

__global__ void rinv_kernel(float* __restrict__ deg) {
    int i = blockIdx.x * blockDim.x + threadIdx.x;
    if (i < RELS * NODES) deg[i] = 1.0f / fmaxf(deg[i], 1.0f);
}

// ---------------- scatter: seg[r][dst] += feat[src], one warp per edge ----------------
template <int D>
__global__ void scatter_kernel(const float* __restrict__ feat, const int* __restrict__ src,
                               const int* __restrict__ dst, float* __restrict__ seg) {
    long gwarp = ((long)blockIdx.x * blockDim.x + threadIdx.x) >> 5;
    int lane = threadIdx.x & 31;
    const long total = (long)RELS * EDGES;
    if (gwarp >= total) return;
    int r = (int)(gwarp / EDGES);
    int s = src[gwarp];
    int d = dst[gwarp];
    const float4* xin = (const float4*)(feat + (size_t)s * D);
    float* out = seg + ((size_t)r * NODES + d) * D;
#pragma unroll
    for (int i = lane; i < D / 4; i += 32) {
        float4 v = __ldg(&xin[i]);
        asm volatile("red.global.add.v4.f32 [%0], {%1,%2,%3,%4};"
                     :: "l"(out + i * 4), "f"(v.x), "f"(v.y), "f"(v.z), "f"(v.w)
                     : "memory");
    }
}

// ---------------- tf32 tensor-core GEMM with fused concat-A + mean-scale ----------------
// C[M,N] = act( [x | rinv0*seg0 | rinv1*seg1 | rinv2*seg2] @ Wcat + bias )
// A is virtual: chunk = kb/D selects source; per-row scale rinv for chunks 1..3.
// Block tile 128x128, BK=32, 8 warps (2x4), warp tile 64x32, mma m16n8k8 tf32.
#define AS_STRIDE 36
#define BS_STRIDE 136

template <int D>
__global__ __launch_bounds__(256)
void gemm_tf32_kernel(const float* __restrict__ feat, const float* __restrict__ seg,
                      const float* __restrict__ rinv, const float* __restrict__ B,
                      const float* __restrict__ bias, float* __restrict__ C,
                      int M, int N, int K, int doRelu) {
    __shared__ float As[128 * AS_STRIDE];   // [row][k] padded
    __shared__ float Bs[32 * BS_STRIDE];    // [k][n] padded

    const int tid  = threadIdx.x;
    const int lane = tid & 31;
    const int warp = tid >> 5;
    const int warpM = (warp >> 2) * 64;     // 0 or 64
    const int warpN = (warp & 3) * 32;      // 0..96
    const int block_row = blockIdx.x * 128;
    const int block_col = blockIdx.y * 128;

    float acc[4][4][4];
#pragma unroll
    for (int i = 0; i < 4; i++)
#pragma unroll
        for (int j = 0; j < 4; j++)
#pragma unroll
            for (int c = 0; c < 4; c++) acc[i][j][c] = 0.f;

    const int a_r0 = tid >> 3;          // 0..31 (row within pass)
    const int a_c0 = (tid & 7) * 4;     // 0..28
    const int b_r0 = tid >> 5;          // 0..7
    const int b_c0 = (tid & 31) * 4;    // 0..124

    for (int kb = 0; kb < K; kb += 32) {
        // ---- load A tile: virtual concat source ----
        const int chunk = kb / D;
        const int col0 = kb - chunk * D;
        const float* src = (chunk == 0) ? feat : (seg + ((size_t)(chunk - 1) * NODES) * D);
        const float* rv  = (chunk == 0) ? nullptr : (rinv + (size_t)(chunk - 1) * NODES);
#pragma unroll
        for (int p = 0; p < 4; p++) {
            int r = p * 32 + a_r0;
            int gr = block_row + r;
            float4 v = make_float4(0.f, 0.f, 0.f, 0.f);
            float sc = 1.f;
            if (gr < M) {
                v = *(const float4*)(src + (size_t)gr * D + col0 + a_c0);
                if (chunk) sc = rv[gr];
            }
            float* dstp = &As[r * AS_STRIDE + a_c0];
            dstp[0] = __uint_as_float(f2tf32(v.x * sc));
            dstp[1] = __uint_as_float(f2tf32(v.y * sc));
            dstp[2] = __uint_as_float(f2tf32(v.z * sc));
            dstp[3] = __uint_as_float(f2tf32(v.w * sc));
        }
        // ---- load B tile (already tf32 bits) ----
#pragma unroll
        for (int p = 0; p < 4; p++) {
            int r = p * 8 + b_r0;
            float4 v = *(const float4*)(B + (size_t)(kb + r) * N + block_col + b_c0);
            *(float4*)(&Bs[r * BS_STRIDE + b_c0]) = v;
        }
        __syncthreads();

        // ---- compute: 4 k8-steps ----
#pragma unroll
        for (int k8 = 0; k8 < 4; k8++) {
            unsigned a[4][4];
#pragma unroll
            for (int mt = 0; mt < 4; mt++) {
                int row = warpM + mt * 16 + (lane >> 2);
                int col = k8 * 8 + (lane & 3);
                a[mt][0] = __float_as_uint(As[row * AS_STRIDE + col]);
                a[mt][1] = __float_as_uint(As[(row + 8) * AS_STRIDE + col]);
                a[mt][2] = __float_as_uint(As[row * AS_STRIDE + col + 4]);
                a[mt][3] = __float_as_uint(As[(row + 8) * AS_STRIDE + col + 4]);
            }
            unsigned b[4][2];
#pragma unroll
            for (int nt = 0; nt < 4; nt++) {
                int cn = warpN + nt * 8 + (lane >> 2);
                int kr = k8 * 8 + (lane & 3);
                b[nt][0] = __float_as_uint(Bs[kr * BS_STRIDE + cn]);
                b[nt][1] = __float_as_uint(Bs[(kr + 4) * BS_STRIDE + cn]);
            }
#pragma unroll
            for (int mt = 0; mt < 4; mt++)
#pragma unroll
                for (int nt = 0; nt < 4; nt++) {
                    asm volatile(
                        "mma.sync.aligned.m16n8k8.row.col.f32.tf32.tf32.f32 "
                        "{%0,%1,%2,%3}, {%4,%5,%6,%7}, {%8,%9}, {%0,%1,%2,%3};"
                        : "+f"(acc[mt][nt][0]), "+f"(acc[mt][nt][1]),
                          "+f"(acc[mt][nt][2]), "+f"(acc[mt][nt][3])
                        : "r"(a[mt][0]), "r"(a[mt][1]), "r"(a[mt][2]), "r"(a[mt][3]),
                          "r"(b[nt][0]), "r"(b[nt][1]));
                }
        }
        __syncthreads();
    }

    // ---- epilogue ----
#pragma unroll
    for (int mt = 0; mt < 4; mt++) {
#pragma unroll
        for (int nt = 0; nt < 4; nt++) {
            int col = block_col + warpN + nt * 8 + (lane & 3) * 2;
            float bx = bias[col], by = bias[col + 1];
#pragma unroll
            for (int half = 0; half < 2; half++) {
                int row = block_row + warpM + mt * 16 + (lane >> 2) + half * 8;
                if (row >= M) continue;
                float vx = acc[mt][nt][half * 2 + 0] + bx;
                float vy = acc[mt][nt][half * 2 + 1] + by;
                if (doRelu) { vx = fmaxf(vx, 0.f); vy = fmaxf(vy, 0.f); }
                *(float2*)(C + (size_t)row * N + col) = make_float2(vx, vy);
            }
        }
    }
}

// ---------------- launch ----------------
extern "C" void kernel_launch(void* const* d_in, const int* in_sizes, int n_in,
                              void* d_out, int out_size) {
    const float* x      = (const float*)d_in[0];
    const int*   src    = (const int*)  d_in[1];
    const int*   dst    = (const int*)  d_in[2];
    const float* Wself1 = (const float*)d_in[3];
    const float* Wneigh1= (const float*)d_in[4];
    const float* b1     = (const float*)d_in[5];
    const float* Wself2 = (const float*)d_in[6];
    const float* Wneigh2= (const float*)d_in[7];
    const float* b2     = (const float*)d_in[8];
    float* out = (float*)d_out;

    float *seg1, *seg2, *h, *rinv, *W1, *W2, *b1s, *b2s;
    cudaGetSymbolAddress((void**)&seg1, g_seg1);
    cudaGetSymbolAddress((void**)&seg2, g_seg2);
    cudaGetSymbolAddress((void**)&h,    g_h);
    cudaGetSymbolAddress((void**)&rinv, g_rinv);
    cudaGetSymbolAddress((void**)&W1,   g_W1);
    cudaGetSymbolAddress((void**)&W2,   g_W2);
    cudaGetSymbolAddress((void**)&b1s,  g_b1s);
    cudaGetSymbolAddress((void**)&b2s,  g_b2s);

    // ---- zero accumulators + deg ----
    zero_kernel<<<4096, 256>>>((float4*)seg1, (long)RELS * NODES * D_IN / 4);
    zero_kernel<<<4096, 256>>>((float4*)seg2, (long)RELS * NODES * D_HID / 4);
    zero_kernel<<<256, 256>>>((float4*)rinv, (long)RELS * NODES / 4);

    // ---- stacked weights (tf32) / bias ----
    prep_w_kernel<<<(4 * D_IN * D_HID + 255) / 256, 256>>>(Wself1, Wneigh1, b1, W1, b1s, D_IN, D_HID);
    prep_w_kernel<<<(4 * D_HID * D_OUT + 255) / 256, 256>>>(Wself2, Wneigh2, b2, W2, b2s, D_HID, D_OUT);

    // ---- degrees -> reciprocal ----
    deg_kernel<<<(RELS * EDGES + 255) / 256, 256>>>(dst, rinv);
    rinv_kernel<<<(RELS * NODES + 255) / 256, 256>>>(rinv);

    const long total_edges = (long)RELS * EDGES;
    const int scatter_blocks = (int)((total_edges * 32 + 255) / 256);
    const int mblocks = (NODES + 127) / 128;

    // ---- layer 1 ----
    scatter_kernel<D_IN><<<scatter_blocks, 256>>>(x, src, dst, seg1);
    {
        dim3 grid(mblocks, D_HID / 128);
        gemm_tf32_kernel<D_IN><<<grid, 256>>>(x, seg1, rinv, W1, b1s, h,
                                              NODES, D_HID, 4 * D_IN, 1);
    }

    // ---- layer 2 ----
    scatter_kernel<D_HID><<<scatter_blocks, 256>>>(h, src, dst, seg2);
    {
        dim3 grid(mblocks, D_OUT / 128);
        gemm_tf32_kernel<D_HID><<<grid, 256>>>(h, seg2, rinv, W2, b2s, out,
                                               NODES, D_OUT, 4 * D_HID, 0);
    }
}

// round 3
// speedup vs baseline: 1.9545x; 1.2240x over previous
#include <cuda_runtime.h>
#include <cuda_bf16.h>
#include <cstdint>

// ---------------- problem constants ----------------
#define NODES 50000
#define RELS  3
#define EDGES 600000
#define D_IN  128
#define D_HID 256
#define D_OUT 128

// ---------------- scratch ----------------
__device__ float g_seg1[(size_t)RELS * NODES * D_IN];    // 76.8 MB
__device__ float g_h   [(size_t)NODES * D_HID];          // 51.2 MB
__device__ float g_Y   [(size_t)NODES * 4 * D_OUT];      // 102.4 MB: [y0|y1|y2|self]
__device__ float g_acc [(size_t)NODES * D_OUT];          // 25.6 MB merged scatter acc
__device__ float g_rinv[(size_t)RELS * NODES];
__device__ float g_W1  [4 * D_IN * D_HID];               // 512 x 256 (tf32 bits)
__device__ float g_W2t [D_HID * 4 * D_OUT];              // 256 x 512 (tf32 bits)
__device__ float g_b1s [D_HID];
__device__ float g_b2s [D_OUT];

__device__ __forceinline__ unsigned f2tf32(float x) {
    unsigned r;
    asm("cvt.rna.tf32.f32 %0, %1;" : "=r"(r) : "f"(x));
    return r;
}

// ---------------- utility kernels ----------------
__global__ void zero_kernel(float4* __restrict__ p, long n4) {
    long stride = (long)gridDim.x * blockDim.x;
    for (long i = (long)blockIdx.x * blockDim.x + threadIdx.x; i < n4; i += stride)
        p[i] = make_float4(0.f, 0.f, 0.f, 0.f);
}

// W1cat [4*DI, DO]: rows [0,DI) = sum_r Wself_r ; rows DI+r*DI+d = Wneigh[r][d]. tf32 bits.
__global__ void prep_w1_kernel(const float* __restrict__ Wself, const float* __restrict__ Wneigh,
                               const float* __restrict__ b, float* __restrict__ Wcat,
                               float* __restrict__ bs, int DI, int DO) {
    int total = 4 * DI * DO;
    int stride = gridDim.x * blockDim.x;
    for (int idx = blockIdx.x * blockDim.x + threadIdx.x; idx < total; idx += stride) {
        int k = idx / DO;
        int j = idx - k * DO;
        float v;
        if (k < DI) {
            v = Wself[k * DO + j] + Wself[(DI + k) * DO + j] + Wself[(2 * DI + k) * DO + j];
        } else {
            int r = (k - DI) / DI;
            int d = (k - DI) - r * DI;
            v = Wneigh[((size_t)r * DI + d) * DO + j];
        }
        Wcat[idx] = __uint_as_float(f2tf32(v));
    }
    int idx = blockIdx.x * blockDim.x + threadIdx.x;
    if (idx < DO) bs[idx] = b[idx] + b[DO + idx] + b[2 * DO + idx];
}

// W2t [256, 512]: cols [r*128, r*128+128) = Wneigh2_r ; cols [384,512) = sum_r Wself2_r. tf32 bits.
__global__ void prep_w2_kernel(const float* __restrict__ Wself, const float* __restrict__ Wneigh,
                               const float* __restrict__ b, float* __restrict__ Wcat,
                               float* __restrict__ bs) {
    int total = D_HID * 4 * D_OUT;      // 256*512
    int stride = gridDim.x * blockDim.x;
    for (int idx = blockIdx.x * blockDim.x + threadIdx.x; idx < total; idx += stride) {
        int k = idx / (4 * D_OUT);
        int c = idx - k * (4 * D_OUT);
        float v;
        if (c < 3 * D_OUT) {
            int r = c / D_OUT;
            int j = c - r * D_OUT;
            v = Wneigh[((size_t)r * D_HID + k) * D_OUT + j];
        } else {
            int j = c - 3 * D_OUT;
            v = Wself[(size_t)k * D_OUT + j]
              + Wself[((size_t)D_HID + k) * D_OUT + j]
              + Wself[((size_t)2 * D_HID + k) * D_OUT + j];
        }
        Wcat[idx] = __uint_as_float(f2tf32(v));
    }
    int idx = blockIdx.x * blockDim.x + threadIdx.x;
    if (idx < D_OUT) bs[idx] = b[idx] + b[D_OUT + idx] + b[2 * D_OUT + idx];
}

__global__ void deg_kernel(const int* __restrict__ dst, float* __restrict__ deg) {
    int e = blockIdx.x * blockDim.x + threadIdx.x;
    if (e >= RELS * EDGES) return;
    int r = e / EDGES;
    atomicAdd(&deg[r * NODES + dst[e]], 1.0f);
}

__global__ void rinv_kernel(float* __restrict__ deg) {
    int i = blockIdx.x * blockDim.x + threadIdx.x;
    if (i < RELS * NODES) deg[i] = 1.0f / fmaxf(deg[i], 1.0f);
}

// ---------------- scatter L1: seg[r][dst] += x[src], one warp per edge ----------------
__global__ void scatter1_kernel(const float* __restrict__ feat, const int* __restrict__ src,
                                const int* __restrict__ dst, float* __restrict__ seg) {
    long gwarp = ((long)blockIdx.x * blockDim.x + threadIdx.x) >> 5;
    int lane = threadIdx.x & 31;
    const long total = (long)RELS * EDGES;
    if (gwarp >= total) return;
    int r = (int)(gwarp / EDGES);
    int s = src[gwarp];
    int d = dst[gwarp];
    const float4* xin = (const float4*)(feat + (size_t)s * D_IN);
    float* out = seg + ((size_t)r * NODES + d) * D_IN;
    float4 v = __ldg(&xin[lane]);
    asm volatile("red.global.add.v4.f32 [%0], {%1,%2,%3,%4};"
                 :: "l"(out + lane * 4), "f"(v.x), "f"(v.y), "f"(v.z), "f"(v.w)
                 : "memory");
}

// ---------------- scatter L2 (pre-transformed, pre-scaled, merged relations) ----------------
// acc[dst][j] += Y[src][r*128 + j] * rinv[r][dst]
__global__ void scatter2_kernel(const float* __restrict__ Y, const int* __restrict__ src,
                                const int* __restrict__ dst, const float* __restrict__ rinv,
                                float* __restrict__ acc) {
    long gwarp = ((long)blockIdx.x * blockDim.x + threadIdx.x) >> 5;
    int lane = threadIdx.x & 31;
    const long total = (long)RELS * EDGES;
    if (gwarp >= total) return;
    int r = (int)(gwarp / EDGES);
    int s = src[gwarp];
    int d = dst[gwarp];
    float sc = __ldg(&rinv[(size_t)r * NODES + d]);
    const float4* yin = (const float4*)(Y + (size_t)s * (4 * D_OUT) + r * D_OUT);
    float* out = acc + (size_t)d * D_OUT;
    float4 v = __ldg(&yin[lane]);
    asm volatile("red.global.add.v4.f32 [%0], {%1,%2,%3,%4};"
                 :: "l"(out + lane * 4),
                    "f"(v.x * sc), "f"(v.y * sc), "f"(v.z * sc), "f"(v.w * sc)
                 : "memory");
}

// ---------------- final: out = Yself + acc + b ----------------
__global__ void final_kernel(const float* __restrict__ Y, const float* __restrict__ acc,
                             const float* __restrict__ bs, float* __restrict__ out) {
    long total = (long)NODES * D_OUT / 4;
    long stride = (long)gridDim.x * blockDim.x;
    for (long id = (long)blockIdx.x * blockDim.x + threadIdx.x; id < total; id += stride) {
        int n = (int)(id / (D_OUT / 4));
        int c4 = (int)(id - (long)n * (D_OUT / 4));
        float4 ys = *(const float4*)(Y + (size_t)n * (4 * D_OUT) + 3 * D_OUT + c4 * 4);
        float4 ac = ((const float4*)acc)[id];
        float4 bv = *(const float4*)(bs + c4 * 4);
        float4 o;
        o.x = ys.x + ac.x + bv.x;
        o.y = ys.y + ac.y + bv.y;
        o.z = ys.z + ac.z + bv.z;
        o.w = ys.w + ac.w + bv.w;
        ((float4*)out)[id] = o;
    }
}

// ---------------- tf32 tensor-core GEMM with fused concat-A + mean-scale ----------------
// chunk = kb/D selects source (feat for chunk 0, seg_r for 1..3); per-row rinv scale on seg.
// Block tile 128x128, BK=32, 8 warps, warp tile 64x32, mma m16n8k8 tf32.
#define AS_STRIDE 36
#define BS_STRIDE 136

template <int D>
__global__ __launch_bounds__(256)
void gemm_tf32_kernel(const float* __restrict__ feat, const float* __restrict__ seg,
                      const float* __restrict__ rinv, const float* __restrict__ B,
                      const float* __restrict__ bias, float* __restrict__ C,
                      int M, int N, int K, int doRelu, int doBias) {
    __shared__ float As[128 * AS_STRIDE];
    __shared__ float Bs[32 * BS_STRIDE];

    const int tid  = threadIdx.x;
    const int lane = tid & 31;
    const int warp = tid >> 5;
    const int warpM = (warp >> 2) * 64;
    const int warpN = (warp & 3) * 32;
    const int block_row = blockIdx.x * 128;
    const int block_col = blockIdx.y * 128;

    float acc[4][4][4];
#pragma unroll
    for (int i = 0; i < 4; i++)
#pragma unroll
        for (int j = 0; j < 4; j++)
#pragma unroll
            for (int c = 0; c < 4; c++) acc[i][j][c] = 0.f;

    const int a_r0 = tid >> 3;
    const int a_c0 = (tid & 7) * 4;
    const int b_r0 = tid >> 5;
    const int b_c0 = (tid & 31) * 4;

    for (int kb = 0; kb < K; kb += 32) {
        const int chunk = kb / D;
        const int col0 = kb - chunk * D;
        const float* srcp = (chunk == 0) ? feat : (seg + ((size_t)(chunk - 1) * NODES) * D);
        const float* rv   = (chunk == 0) ? nullptr : (rinv + (size_t)(chunk - 1) * NODES);
#pragma unroll
        for (int p = 0; p < 4; p++) {
            int r = p * 32 + a_r0;
            int gr = block_row + r;
            float4 v = make_float4(0.f, 0.f, 0.f, 0.f);
            float sc = 1.f;
            if (gr < M) {
                v = *(const float4*)(srcp + (size_t)gr * D + col0 + a_c0);
                if (chunk) sc = rv[gr];
            }
            float* dstp = &As[r * AS_STRIDE + a_c0];
            dstp[0] = __uint_as_float(f2tf32(v.x * sc));
            dstp[1] = __uint_as_float(f2tf32(v.y * sc));
            dstp[2] = __uint_as_float(f2tf32(v.z * sc));
            dstp[3] = __uint_as_float(f2tf32(v.w * sc));
        }
#pragma unroll
        for (int p = 0; p < 4; p++) {
            int r = p * 8 + b_r0;
            float4 v = *(const float4*)(B + (size_t)(kb + r) * N + block_col + b_c0);
            *(float4*)(&Bs[r * BS_STRIDE + b_c0]) = v;
        }
        __syncthreads();

#pragma unroll
        for (int k8 = 0; k8 < 4; k8++) {
            unsigned a[4][4];
#pragma unroll
            for (int mt = 0; mt < 4; mt++) {
                int row = warpM + mt * 16 + (lane >> 2);
                int col = k8 * 8 + (lane & 3);
                a[mt][0] = __float_as_uint(As[row * AS_STRIDE + col]);
                a[mt][1] = __float_as_uint(As[(row + 8) * AS_STRIDE + col]);
                a[mt][2] = __float_as_uint(As[row * AS_STRIDE + col + 4]);
                a[mt][3] = __float_as_uint(As[(row + 8) * AS_STRIDE + col + 4]);
            }
            unsigned b[4][2];
#pragma unroll
            for (int nt = 0; nt < 4; nt++) {
                int cn = warpN + nt * 8 + (lane >> 2);
                int kr = k8 * 8 + (lane & 3);
                b[nt][0] = __float_as_uint(Bs[kr * BS_STRIDE + cn]);
                b[nt][1] = __float_as_uint(Bs[(kr + 4) * BS_STRIDE + cn]);
            }
#pragma unroll
            for (int mt = 0; mt < 4; mt++)
#pragma unroll
                for (int nt = 0; nt < 4; nt++) {
                    asm volatile(
                        "mma.sync.aligned.m16n8k8.row.col.f32.tf32.tf32.f32 "
                        "{%0,%1,%2,%3}, {%4,%5,%6,%7}, {%8,%9}, {%0,%1,%2,%3};"
                        : "+f"(acc[mt][nt][0]), "+f"(acc[mt][nt][1]),
                          "+f"(acc[mt][nt][2]), "+f"(acc[mt][nt][3])
                        : "r"(a[mt][0]), "r"(a[mt][1]), "r"(a[mt][2]), "r"(a[mt][3]),
                          "r"(b[nt][0]), "r"(b[nt][1]));
                }
        }
        __syncthreads();
    }

#pragma unroll
    for (int mt = 0; mt < 4; mt++) {
#pragma unroll
        for (int nt = 0; nt < 4; nt++) {
            int col = block_col + warpN + nt * 8 + (lane & 3) * 2;
            float bx = doBias ? bias[col] : 0.f;
            float by = doBias ? bias[col + 1] : 0.f;
#pragma unroll
            for (int half = 0; half < 2; half++) {
                int row = block_row + warpM + mt * 16 + (lane >> 2) + half * 8;
                if (row >= M) continue;
                float vx = acc[mt][nt][half * 2 + 0] + bx;
                float vy = acc[mt][nt][half * 2 + 1] + by;
                if (doRelu) { vx = fmaxf(vx, 0.f); vy = fmaxf(vy, 0.f); }
                *(float2*)(C + (size_t)row * N + col) = make_float2(vx, vy);
            }
        }
    }
}

// ---------------- launch ----------------
extern "C" void kernel_launch(void* const* d_in, const int* in_sizes, int n_in,
                              void* d_out, int out_size) {
    const float* x      = (const float*)d_in[0];
    const int*   src    = (const int*)  d_in[1];
    const int*   dst    = (const int*)  d_in[2];
    const float* Wself1 = (const float*)d_in[3];
    const float* Wneigh1= (const float*)d_in[4];
    const float* b1     = (const float*)d_in[5];
    const float* Wself2 = (const float*)d_in[6];
    const float* Wneigh2= (const float*)d_in[7];
    const float* b2     = (const float*)d_in[8];
    float* out = (float*)d_out;

    float *seg1, *h, *Y, *acc, *rinv, *W1, *W2t, *b1s, *b2s;
    cudaGetSymbolAddress((void**)&seg1, g_seg1);
    cudaGetSymbolAddress((void**)&h,    g_h);
    cudaGetSymbolAddress((void**)&Y,    g_Y);
    cudaGetSymbolAddress((void**)&acc,  g_acc);
    cudaGetSymbolAddress((void**)&rinv, g_rinv);
    cudaGetSymbolAddress((void**)&W1,   g_W1);
    cudaGetSymbolAddress((void**)&W2t,  g_W2t);
    cudaGetSymbolAddress((void**)&b1s,  g_b1s);
    cudaGetSymbolAddress((void**)&b2s,  g_b2s);

    // ---- zero accumulators ----
    zero_kernel<<<4096, 256>>>((float4*)seg1, (long)RELS * NODES * D_IN / 4);
    zero_kernel<<<2048, 256>>>((float4*)acc,  (long)NODES * D_OUT / 4);
    zero_kernel<<<256, 256>>>((float4*)rinv,  (long)RELS * NODES / 4);

    // ---- stacked weights (tf32) / bias sums ----
    prep_w1_kernel<<<(4 * D_IN * D_HID + 255) / 256, 256>>>(Wself1, Wneigh1, b1, W1, b1s, D_IN, D_HID);
    prep_w2_kernel<<<(D_HID * 4 * D_OUT + 255) / 256, 256>>>(Wself2, Wneigh2, b2, W2t, b2s);

    // ---- degrees -> reciprocal ----
    deg_kernel<<<(RELS * EDGES + 255) / 256, 256>>>(dst, rinv);
    rinv_kernel<<<(RELS * NODES + 255) / 256, 256>>>(rinv);

    const long total_edges = (long)RELS * EDGES;
    const int scatter_blocks = (int)((total_edges * 32 + 255) / 256);
    const int mblocks = (NODES + 127) / 128;

    // ---- layer 1: scatter x -> seg1, then fused-concat GEMM -> h (relu) ----
    scatter1_kernel<<<scatter_blocks, 256>>>(x, src, dst, seg1);
    {
        dim3 grid(mblocks, D_HID / 128);
        gemm_tf32_kernel<D_IN><<<grid, 256>>>(x, seg1, rinv, W1, b1s, h,
                                              NODES, D_HID, 4 * D_IN, 1, 1);
    }

    // ---- layer 2: transform-first GEMM -> Y = h @ [Wn0|Wn1|Wn2|Wself_sum] ----
    {
        dim3 grid(mblocks, (4 * D_OUT) / 128);
        gemm_tf32_kernel<D_HID><<<grid, 256>>>(h, nullptr, rinv, W2t, nullptr, Y,
                                               NODES, 4 * D_OUT, D_HID, 0, 0);
    }
    // scatter pre-scaled transformed features into merged 128-dim accumulator
    scatter2_kernel<<<scatter_blocks, 256>>>(Y, src, dst, rinv, acc);
    // out = Yself + acc + b2s
    final_kernel<<<2048, 256>>>(Y, acc, b2s, out);
}

// round 4
// speedup vs baseline: 3.6460x; 1.8655x over previous
#include <cuda_runtime.h>
#include <cuda_bf16.h>
#include <cstdint>

// ---------------- problem constants ----------------
#define NODES 50000
#define RELS  3
#define EDGES 600000
#define D_IN  128
#define D_HID 256
#define D_OUT 128

#define SCAN_N (RELS * NODES)          // 150000 segments
#define SCAN_B 512
#define SCAN_BLOCKS ((SCAN_N + SCAN_B - 1) / SCAN_B)   // 293

// ---------------- scratch ----------------
__device__ float g_seg1[(size_t)RELS * NODES * D_IN];    // 76.8 MB  (means, layer 1)
__device__ float g_h   [(size_t)NODES * D_HID];          // 51.2 MB
__device__ float g_Y   [(size_t)NODES * 4 * D_OUT];      // 102.4 MB: [y0|y1|y2|self]
__device__ float g_acc [(size_t)NODES * D_OUT];          // 25.6 MB
__device__ int   g_csr [2 * SCAN_N];                     // cnt | cur
__device__ int   g_offs[SCAN_N + 1];
__device__ int   g_bsum[SCAN_B];
__device__ int   g_elist[(size_t)RELS * EDGES];          // 7.2 MB
__device__ float g_W1  [4 * D_IN * D_HID];               // 512 x 256 (tf32 bits)
__device__ float g_W2t [D_HID * 4 * D_OUT];              // 256 x 512 (tf32 bits)
__device__ float g_b1s [D_HID];
__device__ float g_b2s [D_OUT];

__device__ __forceinline__ unsigned f2tf32(float x) {
    unsigned r;
    asm("cvt.rna.tf32.f32 %0, %1;" : "=r"(r) : "f"(x));
    return r;
}

// ---------------- utility ----------------
__global__ void zero_f4(float4* __restrict__ p, long n4) {
    long stride = (long)gridDim.x * blockDim.x;
    for (long i = (long)blockIdx.x * blockDim.x + threadIdx.x; i < n4; i += stride)
        p[i] = make_float4(0.f, 0.f, 0.f, 0.f);
}
__global__ void zero_i(int* __restrict__ p, int n) {
    int i = blockIdx.x * blockDim.x + threadIdx.x;
    if (i < n) p[i] = 0;
}

// W1cat [4*DI, DO]: rows [0,DI)=sum_r Wself_r ; rows DI+r*DI+d = Wneigh[r][d]. tf32 bits.
__global__ void prep_w1_kernel(const float* __restrict__ Wself, const float* __restrict__ Wneigh,
                               const float* __restrict__ b, float* __restrict__ Wcat,
                               float* __restrict__ bs, int DI, int DO) {
    int total = 4 * DI * DO;
    int stride = gridDim.x * blockDim.x;
    for (int idx = blockIdx.x * blockDim.x + threadIdx.x; idx < total; idx += stride) {
        int k = idx / DO;
        int j = idx - k * DO;
        float v;
        if (k < DI) {
            v = Wself[k * DO + j] + Wself[(DI + k) * DO + j] + Wself[(2 * DI + k) * DO + j];
        } else {
            int r = (k - DI) / DI;
            int d = (k - DI) - r * DI;
            v = Wneigh[((size_t)r * DI + d) * DO + j];
        }
        Wcat[idx] = __uint_as_float(f2tf32(v));
    }
    int idx = blockIdx.x * blockDim.x + threadIdx.x;
    if (idx < DO) bs[idx] = b[idx] + b[DO + idx] + b[2 * DO + idx];
}

// W2t [256, 512]: cols [r*128,..) = Wneigh2_r ; cols [384,512) = sum_r Wself2_r. tf32 bits.
__global__ void prep_w2_kernel(const float* __restrict__ Wself, const float* __restrict__ Wneigh,
                               const float* __restrict__ b, float* __restrict__ Wcat,
                               float* __restrict__ bs) {
    int total = D_HID * 4 * D_OUT;
    int stride = gridDim.x * blockDim.x;
    for (int idx = blockIdx.x * blockDim.x + threadIdx.x; idx < total; idx += stride) {
        int k = idx / (4 * D_OUT);
        int c = idx - k * (4 * D_OUT);
        float v;
        if (c < 3 * D_OUT) {
            int r = c / D_OUT;
            int j = c - r * D_OUT;
            v = Wneigh[((size_t)r * D_HID + k) * D_OUT + j];
        } else {
            int j = c - 3 * D_OUT;
            v = Wself[(size_t)k * D_OUT + j]
              + Wself[((size_t)D_HID + k) * D_OUT + j]
              + Wself[((size_t)2 * D_HID + k) * D_OUT + j];
        }
        Wcat[idx] = __uint_as_float(f2tf32(v));
    }
    int idx = blockIdx.x * blockDim.x + threadIdx.x;
    if (idx < D_OUT) bs[idx] = b[idx] + b[D_OUT + idx] + b[2 * D_OUT + idx];
}

// ---------------- CSR build ----------------
__global__ void cnt_kernel(const int* __restrict__ dst, int* __restrict__ cnt) {
    int e = blockIdx.x * blockDim.x + threadIdx.x;
    if (e >= RELS * EDGES) return;
    int r = e / EDGES;
    atomicAdd(&cnt[r * NODES + dst[e]], 1);
}

__global__ void scan1_kernel(const int* __restrict__ cnt, int* __restrict__ offs,
                             int* __restrict__ bsum) {
    __shared__ int sm[SCAN_B];
    int i = blockIdx.x * SCAN_B + threadIdx.x;
    int v = (i < SCAN_N) ? cnt[i] : 0;
    sm[threadIdx.x] = v;
    __syncthreads();
#pragma unroll
    for (int off = 1; off < SCAN_B; off <<= 1) {
        int t = (threadIdx.x >= off) ? sm[threadIdx.x - off] : 0;
        __syncthreads();
        sm[threadIdx.x] += t;
        __syncthreads();
    }
    int incl = sm[threadIdx.x];
    if (i < SCAN_N) offs[i] = incl - v;
    if (threadIdx.x == SCAN_B - 1) bsum[blockIdx.x] = incl;
}

__global__ void scan2_kernel(int* __restrict__ bsum, int nb) {
    __shared__ int sm[SCAN_B];
    int v = (threadIdx.x < nb) ? bsum[threadIdx.x] : 0;
    sm[threadIdx.x] = v;
    __syncthreads();
#pragma unroll
    for (int off = 1; off < SCAN_B; off <<= 1) {
        int t = (threadIdx.x >= off) ? sm[threadIdx.x - off] : 0;
        __syncthreads();
        sm[threadIdx.x] += t;
        __syncthreads();
    }
    if (threadIdx.x < nb) bsum[threadIdx.x] = sm[threadIdx.x] - v;
}

__global__ void scan3_kernel(int* __restrict__ offs, const int* __restrict__ bsum) {
    int i = blockIdx.x * SCAN_B + threadIdx.x;
    if (i < SCAN_N) offs[i] += bsum[blockIdx.x];
    if (i == 0) offs[SCAN_N] = RELS * EDGES;
}

__global__ void fill_kernel(const int* __restrict__ src, const int* __restrict__ dst,
                            const int* __restrict__ offs, int* __restrict__ cur,
                            int* __restrict__ elist) {
    int e = blockIdx.x * blockDim.x + threadIdx.x;
    if (e >= RELS * EDGES) return;
    int r = e / EDGES;
    int idx = r * NODES + dst[e];
    int pos = offs[idx] + atomicAdd(&cur[idx], 1);
    elist[pos] = src[e];
}

// ---------------- reduce 1: seg[r*NODES+d] = mean of x[src] over edge list ----------------
__global__ void reduce1_kernel(const float* __restrict__ x, const int* __restrict__ offs,
                               const int* __restrict__ elist, float* __restrict__ seg) {
    int w = (blockIdx.x * blockDim.x + threadIdx.x) >> 5;
    int lane = threadIdx.x & 31;
    if (w >= SCAN_N) return;
    int beg = offs[w], end = offs[w + 1];
    float4 s = make_float4(0.f, 0.f, 0.f, 0.f);
    for (int i = beg; i < end; i += 32) {
        int nid = (i + lane < end) ? elist[i + lane] : 0;
        int cnt = min(32, end - i);
        for (int j = 0; j < cnt; j++) {
            int sid = __shfl_sync(0xffffffffu, nid, j);
            float4 v = __ldg(((const float4*)(x + (size_t)sid * D_IN)) + lane);
            s.x += v.x; s.y += v.y; s.z += v.z; s.w += v.w;
        }
    }
    float sc = 1.f / fmaxf((float)(end - beg), 1.f);
    s.x *= sc; s.y *= sc; s.z *= sc; s.w *= sc;
    ((float4*)(seg + (size_t)w * D_IN))[lane] = s;
}

// ---------------- reduce 2: acc[d] += (1/deg) * sum_e Y[src, r*128..] ----------------
__global__ void reduce2_kernel(const float* __restrict__ Y, const int* __restrict__ offs,
                               const int* __restrict__ elist, float* __restrict__ acc) {
    int w = (blockIdx.x * blockDim.x + threadIdx.x) >> 5;
    int lane = threadIdx.x & 31;
    if (w >= SCAN_N) return;
    int r = w / NODES;
    int d = w - r * NODES;
    int beg = offs[w], end = offs[w + 1];
    if (beg == end) return;
    float4 s = make_float4(0.f, 0.f, 0.f, 0.f);
    for (int i = beg; i < end; i += 32) {
        int nid = (i + lane < end) ? elist[i + lane] : 0;
        int cnt = min(32, end - i);
        for (int j = 0; j < cnt; j++) {
            int sid = __shfl_sync(0xffffffffu, nid, j);
            float4 v = __ldg(((const float4*)(Y + (size_t)sid * (4 * D_OUT) + r * D_OUT)) + lane);
            s.x += v.x; s.y += v.y; s.z += v.z; s.w += v.w;
        }
    }
    float sc = 1.f / (float)(end - beg);
    float* out = acc + (size_t)d * D_OUT + lane * 4;
    asm volatile("red.global.add.v4.f32 [%0], {%1,%2,%3,%4};"
                 :: "l"(out), "f"(s.x * sc), "f"(s.y * sc), "f"(s.z * sc), "f"(s.w * sc)
                 : "memory");
}

// ---------------- final: out = Yself + acc + b ----------------
__global__ void final_kernel(const float* __restrict__ Y, const float* __restrict__ acc,
                             const float* __restrict__ bs, float* __restrict__ out) {
    long total = (long)NODES * D_OUT / 4;
    long stride = (long)gridDim.x * blockDim.x;
    for (long id = (long)blockIdx.x * blockDim.x + threadIdx.x; id < total; id += stride) {
        int n = (int)(id / (D_OUT / 4));
        int c4 = (int)(id - (long)n * (D_OUT / 4));
        float4 ys = *(const float4*)(Y + (size_t)n * (4 * D_OUT) + 3 * D_OUT + c4 * 4);
        float4 ac = ((const float4*)acc)[id];
        float4 bv = *(const float4*)(bs + c4 * 4);
        ((float4*)out)[id] = make_float4(ys.x + ac.x + bv.x, ys.y + ac.y + bv.y,
                                         ys.z + ac.z + bv.z, ys.w + ac.w + bv.w);
    }
}

// ---------------- cp.async double-buffered tf32 GEMM, fused concat-A ----------------
#define ASTRIDE 36
#define BSTRIDE 136
#define A_TILE (128 * ASTRIDE)
#define B_TILE (32 * BSTRIDE)
#define GEMM_SMEM ((2 * A_TILE + 2 * B_TILE) * 4)

template <int D>
__global__ __launch_bounds__(256)
void gemm_tf32_kernel(const float* __restrict__ feat, const float* __restrict__ seg,
                      const float* __restrict__ Bw, const float* __restrict__ bias,
                      float* __restrict__ C, int M, int N, int K, int doRelu, int doBias) {
    extern __shared__ float smp[];
    float* As = smp;
    float* Bs = smp + 2 * A_TILE;
    const uint32_t As_u = (uint32_t)__cvta_generic_to_shared(As);
    const uint32_t Bs_u = (uint32_t)__cvta_generic_to_shared(Bs);

    const int tid  = threadIdx.x;
    const int lane = tid & 31;
    const int warp = tid >> 5;
    const int warpM = (warp >> 2) * 64;
    const int warpN = (warp & 3) * 32;
    const int block_row = blockIdx.x * 128;
    const int block_col = blockIdx.y * 128;

    const int a_r0 = tid >> 3;          // 0..31
    const int a_c0 = (tid & 7) * 4;     // 0..28
    const int b_r0 = tid >> 5;          // 0..7
    const int b_c0 = (tid & 31) * 4;    // 0..124

    float acc[4][4][4];
#pragma unroll
    for (int i = 0; i < 4; i++)
#pragma unroll
        for (int j = 0; j < 4; j++)
#pragma unroll
            for (int c = 0; c < 4; c++) acc[i][j][c] = 0.f;

    auto load_stage = [&](int buf, int kb) {
        const int chunk = kb / D;
        const int col0 = kb - chunk * D;
        const float* base = (chunk == 0) ? feat : (seg + (size_t)(chunk - 1) * NODES * D);
#pragma unroll
        for (int p = 0; p < 4; p++) {
            int r = p * 32 + a_r0;
            int gr = block_row + r;
            const float* g = base + (size_t)gr * D + col0 + a_c0;
            uint32_t sa = As_u + (uint32_t)(buf * A_TILE + r * ASTRIDE + a_c0) * 4u;
            int sz = (gr < M) ? 16 : 0;
            asm volatile("cp.async.cg.shared.global [%0], [%1], 16, %2;"
                         :: "r"(sa), "l"(g), "r"(sz));
        }
#pragma unroll
        for (int p = 0; p < 4; p++) {
            int r = p * 8 + b_r0;
            const float* g = Bw + (size_t)(kb + r) * N + block_col + b_c0;
            uint32_t sa = Bs_u + (uint32_t)(buf * B_TILE + r * BSTRIDE + b_c0) * 4u;
            asm volatile("cp.async.cg.shared.global [%0], [%1], 16;"
                         :: "r"(sa), "l"(g));
        }
        asm volatile("cp.async.commit_group;");
    };

    const int T = K / 32;
    load_stage(0, 0);

    for (int t = 0; t < T; t++) {
        int buf = t & 1;
        if (t + 1 < T) {
            load_stage(buf ^ 1, (t + 1) * 32);
            asm volatile("cp.async.wait_group 1;");
        } else {
            asm volatile("cp.async.wait_group 0;");
        }
        __syncthreads();

        const float* At = As + buf * A_TILE;
        const float* Bt = Bs + buf * B_TILE;
#pragma unroll
        for (int k8 = 0; k8 < 4; k8++) {
            unsigned a[4][4];
#pragma unroll
            for (int mt = 0; mt < 4; mt++) {
                int row = warpM + mt * 16 + (lane >> 2);
                int col = k8 * 8 + (lane & 3);
                a[mt][0] = __float_as_uint(At[row * ASTRIDE + col]);
                a[mt][1] = __float_as_uint(At[(row + 8) * ASTRIDE + col]);
                a[mt][2] = __float_as_uint(At[row * ASTRIDE + col + 4]);
                a[mt][3] = __float_as_uint(At[(row + 8) * ASTRIDE + col + 4]);
            }
            unsigned b[4][2];
#pragma unroll
            for (int nt = 0; nt < 4; nt++) {
                int cn = warpN + nt * 8 + (lane >> 2);
                int kr = k8 * 8 + (lane & 3);
                b[nt][0] = __float_as_uint(Bt[kr * BSTRIDE + cn]);
                b[nt][1] = __float_as_uint(Bt[(kr + 4) * BSTRIDE + cn]);
            }
#pragma unroll
            for (int mt = 0; mt < 4; mt++)
#pragma unroll
                for (int nt = 0; nt < 4; nt++) {
                    asm volatile(
                        "mma.sync.aligned.m16n8k8.row.col.f32.tf32.tf32.f32 "
                        "{%0,%1,%2,%3}, {%4,%5,%6,%7}, {%8,%9}, {%0,%1,%2,%3};"
                        : "+f"(acc[mt][nt][0]), "+f"(acc[mt][nt][1]),
                          "+f"(acc[mt][nt][2]), "+f"(acc[mt][nt][3])
                        : "r"(a[mt][0]), "r"(a[mt][1]), "r"(a[mt][2]), "r"(a[mt][3]),
                          "r"(b[nt][0]), "r"(b[nt][1]));
                }
        }
        __syncthreads();
    }

#pragma unroll
    for (int mt = 0; mt < 4; mt++) {
#pragma unroll
        for (int nt = 0; nt < 4; nt++) {
            int col = block_col + warpN + nt * 8 + (lane & 3) * 2;
            float bx = doBias ? bias[col] : 0.f;
            float by = doBias ? bias[col + 1] : 0.f;
#pragma unroll
            for (int half = 0; half < 2; half++) {
                int row = block_row + warpM + mt * 16 + (lane >> 2) + half * 8;
                if (row >= M) continue;
                float vx = acc[mt][nt][half * 2 + 0] + bx;
                float vy = acc[mt][nt][half * 2 + 1] + by;
                if (doRelu) { vx = fmaxf(vx, 0.f); vy = fmaxf(vy, 0.f); }
                *(float2*)(C + (size_t)row * N + col) = make_float2(vx, vy);
            }
        }
    }
}

// ---------------- launch ----------------
extern "C" void kernel_launch(void* const* d_in, const int* in_sizes, int n_in,
                              void* d_out, int out_size) {
    const float* x      = (const float*)d_in[0];
    const int*   src    = (const int*)  d_in[1];
    const int*   dst    = (const int*)  d_in[2];
    const float* Wself1 = (const float*)d_in[3];
    const float* Wneigh1= (const float*)d_in[4];
    const float* b1     = (const float*)d_in[5];
    const float* Wself2 = (const float*)d_in[6];
    const float* Wneigh2= (const float*)d_in[7];
    const float* b2     = (const float*)d_in[8];
    float* out = (float*)d_out;

    float *seg1, *h, *Y, *acc, *W1, *W2t, *b1s, *b2s;
    int *csr, *offs, *bsum, *elist;
    cudaGetSymbolAddress((void**)&seg1, g_seg1);
    cudaGetSymbolAddress((void**)&h,    g_h);
    cudaGetSymbolAddress((void**)&Y,    g_Y);
    cudaGetSymbolAddress((void**)&acc,  g_acc);
    cudaGetSymbolAddress((void**)&csr,  g_csr);
    cudaGetSymbolAddress((void**)&offs, g_offs);
    cudaGetSymbolAddress((void**)&bsum, g_bsum);
    cudaGetSymbolAddress((void**)&elist,g_elist);
    cudaGetSymbolAddress((void**)&W1,   g_W1);
    cudaGetSymbolAddress((void**)&W2t,  g_W2t);
    cudaGetSymbolAddress((void**)&b1s,  g_b1s);
    cudaGetSymbolAddress((void**)&b2s,  g_b2s);

    cudaFuncSetAttribute(gemm_tf32_kernel<D_IN>,
                         cudaFuncAttributeMaxDynamicSharedMemorySize, GEMM_SMEM);
    cudaFuncSetAttribute(gemm_tf32_kernel<D_HID>,
                         cudaFuncAttributeMaxDynamicSharedMemorySize, GEMM_SMEM);

    int* cnt = csr;
    int* cur = csr + SCAN_N;

    // ---- zero: cnt+cur, acc ----
    zero_i<<<(2 * SCAN_N + 255) / 256, 256>>>(csr, 2 * SCAN_N);
    zero_f4<<<2048, 256>>>((float4*)acc, (long)NODES * D_OUT / 4);

    // ---- stacked weights (tf32) / bias sums ----
    prep_w1_kernel<<<(4 * D_IN * D_HID + 255) / 256, 256>>>(Wself1, Wneigh1, b1, W1, b1s, D_IN, D_HID);
    prep_w2_kernel<<<(D_HID * 4 * D_OUT + 255) / 256, 256>>>(Wself2, Wneigh2, b2, W2t, b2s);

    // ---- CSR build ----
    cnt_kernel<<<(RELS * EDGES + 255) / 256, 256>>>(dst, cnt);
    scan1_kernel<<<SCAN_BLOCKS, SCAN_B>>>(cnt, offs, bsum);
    scan2_kernel<<<1, SCAN_B>>>(bsum, SCAN_BLOCKS);
    scan3_kernel<<<SCAN_BLOCKS, SCAN_B>>>(offs, bsum);
    fill_kernel<<<(RELS * EDGES + 255) / 256, 256>>>(src, dst, offs, cur, elist);

    const int reduce_blocks = (SCAN_N * 32 + 255) / 256;
    const int mblocks = (NODES + 127) / 128;

    // ---- layer 1: means -> seg1, fused-concat GEMM -> h (relu+bias) ----
    reduce1_kernel<<<reduce_blocks, 256>>>(x, offs, elist, seg1);
    {
        dim3 grid(mblocks, D_HID / 128);
        gemm_tf32_kernel<D_IN><<<grid, 256, GEMM_SMEM>>>(x, seg1, W1, b1s, h,
                                                         NODES, D_HID, 4 * D_IN, 1, 1);
    }

    // ---- layer 2: transform-first GEMM -> Y, then CSR reduce, then final add ----
    {
        dim3 grid(mblocks, (4 * D_OUT) / 128);
        gemm_tf32_kernel<D_HID><<<grid, 256, GEMM_SMEM>>>(h, nullptr, W2t, nullptr, Y,
                                                          NODES, 4 * D_OUT, D_HID, 0, 0);
    }
    reduce2_kernel<<<reduce_blocks, 256>>>(Y, offs, elist, acc);
    final_kernel<<<2048, 256>>>(Y, acc, b2s, out);
}